// round 1
// baseline (speedup 1.0000x reference)
#include <cuda_runtime.h>

#define N_NODES 50000
#define N_EDGES 800000
#define NFEAT   256
#define NHID    128
#define ZDIM    32
#define NPAIRS  10000

// ---- scratch (static device globals; no allocation at runtime) ----
__device__ float g_buf_h [(size_t)N_NODES * NHID];  // x @ W result
__device__ float g_buf_x0[(size_t)N_NODES * NHID];  // layer activations
__device__ float g_buf_x1[(size_t)N_NODES * NHID];
__device__ int   g_rowptr[N_NODES + 1];

// ------------------------------------------------------------------
// row_ptr from sorted COO rows: rp[r] = lower_bound(adj_row, r)
// ------------------------------------------------------------------
__global__ void rowptr_kernel(const int* __restrict__ row) {
    int r = blockIdx.x * blockDim.x + threadIdx.x;
    if (r > N_NODES) return;
    int lo = 0, hi = N_EDGES;
    while (lo < hi) {
        int mid = (lo + hi) >> 1;
        if (row[mid] < r) lo = mid + 1; else hi = mid;
    }
    g_rowptr[r] = lo;
}

// ------------------------------------------------------------------
// C[M,128] = A[M,K] @ B[K,128]   (BM=128, BN=128, BK=16; 8x8/thread)
// ------------------------------------------------------------------
__global__ __launch_bounds__(256) void sgemm_n128(
    const float* __restrict__ A, const float* __restrict__ B,
    float* __restrict__ C, int M, int K)
{
    __shared__ float As[16][132];   // [kk][row], padded
    __shared__ float Bs[16][128];   // [kk][col]

    int tid = threadIdx.x;
    int tx = tid & 15, ty = tid >> 4;
    int row0 = blockIdx.x * 128;

    float acc[8][8];
#pragma unroll
    for (int i = 0; i < 8; i++)
#pragma unroll
        for (int j = 0; j < 8; j++) acc[i][j] = 0.f;

    for (int k0 = 0; k0 < K; k0 += 16) {
#pragma unroll
        for (int t = 0; t < 8; t++) {
            int i2 = tid + t * 256;            // 2048 elems of A tile
            int r = i2 >> 4, kk = i2 & 15;
            int gr = row0 + r;
            As[kk][r] = (gr < M) ? A[(size_t)gr * K + k0 + kk] : 0.f;
        }
#pragma unroll
        for (int t = 0; t < 8; t++) {
            int i2 = tid + t * 256;            // 2048 elems of B tile
            int kk = i2 >> 7, c = i2 & 127;
            Bs[kk][c] = B[(size_t)(k0 + kk) * 128 + c];
        }
        __syncthreads();

#pragma unroll
        for (int kk = 0; kk < 16; kk++) {
            float a[8], b[8];
#pragma unroll
            for (int i = 0; i < 8; i++) a[i] = As[kk][ty + 16 * i];
#pragma unroll
            for (int j = 0; j < 8; j++) b[j] = Bs[kk][tx + 16 * j];
#pragma unroll
            for (int i = 0; i < 8; i++)
#pragma unroll
                for (int j = 0; j < 8; j++)
                    acc[i][j] = fmaf(a[i], b[j], acc[i][j]);
        }
        __syncthreads();
    }

#pragma unroll
    for (int i = 0; i < 8; i++) {
        int gr = row0 + ty + 16 * i;
        if (gr < M) {
#pragma unroll
            for (int j = 0; j < 8; j++)
                C[(size_t)gr * 128 + tx + 16 * j] = acc[i][j];
        }
    }
}

// ------------------------------------------------------------------
// SpMM: out[r,:] = relu( sum_e val[e]*H[col[e],:]  + bias ) (+ res)
// one warp per destination row; sorted rows -> contiguous edge range
// ------------------------------------------------------------------
__global__ __launch_bounds__(256) void spmm_kernel(
    const float* __restrict__ H, const int* __restrict__ col,
    const float* __restrict__ val, const float* __restrict__ bias,
    const float* __restrict__ res, float* __restrict__ out)
{
    int w = (blockIdx.x * blockDim.x + threadIdx.x) >> 5;
    if (w >= N_NODES) return;
    int lane = threadIdx.x & 31;

    float a0 = 0.f, a1 = 0.f, a2 = 0.f, a3 = 0.f;
    int s = g_rowptr[w], e = g_rowptr[w + 1];
    for (int i = s; i < e; i++) {
        int   c = __ldg(&col[i]);
        float v = __ldg(&val[i]);
        const float* hrow = H + (size_t)c * 128;
        a0 = fmaf(v, __ldg(hrow + lane),      a0);
        a1 = fmaf(v, __ldg(hrow + lane + 32), a1);
        a2 = fmaf(v, __ldg(hrow + lane + 64), a2);
        a3 = fmaf(v, __ldg(hrow + lane + 96), a3);
    }
    size_t base = (size_t)w * 128;
    float o0 = fmaxf(a0 + bias[lane],      0.f);
    float o1 = fmaxf(a1 + bias[lane + 32], 0.f);
    float o2 = fmaxf(a2 + bias[lane + 64], 0.f);
    float o3 = fmaxf(a3 + bias[lane + 96], 0.f);
    if (res) {
        o0 += res[base + lane];
        o1 += res[base + lane + 32];
        o2 += res[base + lane + 64];
        o3 += res[base + lane + 96];
    }
    out[base + lane]      = o0;
    out[base + lane + 32] = o1;
    out[base + lane + 64] = o2;
    out[base + lane + 96] = o3;
}

// ------------------------------------------------------------------
// Fused decoder: bilinear -> ELU -> MLP(32->32->1) -> predictions
// Block handles 32 pairs. feat[p,k] = a_p^T W_k b_p.
// ------------------------------------------------------------------
__device__ __forceinline__ float elu1(float x) {
    return x > 0.f ? x : expm1f(x);
}

__global__ __launch_bounds__(256) void decode_kernel(
    const float* __restrict__ latent, const int* __restrict__ idx,
    const float* __restrict__ bilw, const float* __restrict__ bilb,
    const float* __restrict__ dw1, const float* __restrict__ db1,
    const float* __restrict__ dw2, const float* __restrict__ db2,
    float* __restrict__ pred)
{
    __shared__ float sA[32][128];   // a rows for 32 pairs
    __shared__ float sB[32][128];   // b rows
    __shared__ float sW[16][128];   // W_k d-chunk
    __shared__ float sF[32][32];    // elu(bilinear) features

    int tid  = threadIdx.x;
    int lane = tid & 31, warp = tid >> 5;
    int p0 = blockIdx.x * 32;

    // gather a/b rows (clamped for tail block; results discarded there)
#pragma unroll
    for (int t = 0; t < 16; t++) {
        int i2 = tid + t * 256;            // 4096 = 32*128
        int p = i2 >> 7, c = i2 & 127;
        int pg = p0 + p; if (pg >= NPAIRS) pg = NPAIRS - 1;
        int na = idx[pg];
        int nb = idx[NPAIRS + pg];
        sA[p][c] = latent[(size_t)na * 128 + c];
        sB[p][c] = latent[(size_t)nb * 128 + c];
    }
    __syncthreads();

    // warp owns pairs [warp*4, warp*4+4); lane owns cols [lane*4, lane*4+4)
    for (int k = 0; k < ZDIM; k++) {
        float4 acc[4];
#pragma unroll
        for (int i = 0; i < 4; i++) acc[i] = make_float4(0.f, 0.f, 0.f, 0.f);

        for (int dc = 0; dc < 8; dc++) {
#pragma unroll
            for (int t = 0; t < 8; t++) {
                int i2 = tid + t * 256;    // 2048 = 16*128
                int dd = i2 >> 7, c = i2 & 127;
                sW[dd][c] = bilw[((size_t)k * 128 + dc * 16 + dd) * 128 + c];
            }
            __syncthreads();
#pragma unroll
            for (int dd = 0; dd < 16; dd++) {
                float4 wv = *(const float4*)&sW[dd][lane * 4];
#pragma unroll
                for (int i = 0; i < 4; i++) {
                    float a = sA[warp * 4 + i][dc * 16 + dd];
                    acc[i].x = fmaf(a, wv.x, acc[i].x);
                    acc[i].y = fmaf(a, wv.y, acc[i].y);
                    acc[i].z = fmaf(a, wv.z, acc[i].z);
                    acc[i].w = fmaf(a, wv.w, acc[i].w);
                }
            }
            __syncthreads();
        }
        // dot with b, warp-reduce over the 128 cols
#pragma unroll
        for (int i = 0; i < 4; i++) {
            float4 b4 = *(const float4*)&sB[warp * 4 + i][lane * 4];
            float part = acc[i].x * b4.x + acc[i].y * b4.y
                       + acc[i].z * b4.z + acc[i].w * b4.w;
#pragma unroll
            for (int off = 16; off; off >>= 1)
                part += __shfl_xor_sync(0xffffffffu, part, off);
            if (lane == 0)
                sF[warp * 4 + i][k] = elu1(part + bilb[k]);
        }
    }
    __syncthreads();

    // tiny MLP: 32 threads, one pair each
    if (tid < 32) {
        int pg = p0 + tid;
        if (pg < NPAIRS) {
            float h[ZDIM];
#pragma unroll
            for (int kk = 0; kk < ZDIM; kk++) {
                float s = db1[kk];
#pragma unroll
                for (int j = 0; j < ZDIM; j++)
                    s = fmaf(sF[tid][j], dw1[j * ZDIM + kk], s);
                h[kk] = elu1(s);
            }
            float o = db2[0];
#pragma unroll
            for (int kk = 0; kk < ZDIM; kk++)
                o = fmaf(h[kk], dw2[kk], o);
            pred[pg] = o;
        }
    }
}

// ------------------------------------------------------------------
extern "C" void kernel_launch(void* const* d_in, const int* in_sizes, int n_in,
                              void* d_out, int out_size)
{
    const float* features = (const float*)d_in[0];
    const int*   adj_row  = (const int*)  d_in[1];
    const int*   adj_col  = (const int*)  d_in[2];
    const float* adj_val  = (const float*)d_in[3];
    const int*   idx      = (const int*)  d_in[4];
    const float* W0   = (const float*)d_in[5];
    const float* b0   = (const float*)d_in[6];
    const float* W1   = (const float*)d_in[7];
    const float* b1   = (const float*)d_in[8];
    const float* W2   = (const float*)d_in[9];
    const float* b2   = (const float*)d_in[10];
    const float* bilw = (const float*)d_in[11];
    const float* bilb = (const float*)d_in[12];
    const float* dw1  = (const float*)d_in[13];
    const float* db1  = (const float*)d_in[14];
    const float* dw2  = (const float*)d_in[15];
    const float* db2  = (const float*)d_in[16];

    float* out    = (float*)d_out;
    float* pred   = out;            // [NPAIRS]
    float* latent = out + NPAIRS;   // [N_NODES * NHID]

    float* h;  cudaGetSymbolAddress((void**)&h,  g_buf_h);
    float* x0; cudaGetSymbolAddress((void**)&x0, g_buf_x0);
    float* x1; cudaGetSymbolAddress((void**)&x1, g_buf_x1);

    // row_ptr
    rowptr_kernel<<<(N_NODES + 1 + 255) / 256, 256>>>(adj_row);

    const int gemm_grid = (N_NODES + 127) / 128;
    const int spmm_grid = (N_NODES * 32 + 255) / 256;

    // layer 0: x0 = relu(A @ (features @ W0) + b0)
    sgemm_n128<<<gemm_grid, 256>>>(features, W0, h, N_NODES, NFEAT);
    spmm_kernel<<<spmm_grid, 256>>>(h, adj_col, adj_val, b0, nullptr, x0);

    // layer 1: x1 = relu(A @ (x0 @ W1) + b1) + x0
    sgemm_n128<<<gemm_grid, 256>>>(x0, W1, h, N_NODES, NHID);
    spmm_kernel<<<spmm_grid, 256>>>(h, adj_col, adj_val, b1, x0, x1);

    // layer 2: latent = relu(A @ (x1 @ W2) + b2) + x1   (written to d_out)
    sgemm_n128<<<gemm_grid, 256>>>(x1, W2, h, N_NODES, NHID);
    spmm_kernel<<<spmm_grid, 256>>>(h, adj_col, adj_val, b2, x1, latent);

    // decoder: bilinear + ELU + MLP -> predictions
    decode_kernel<<<(NPAIRS + 31) / 32, 256>>>(latent, idx, bilw, bilb,
                                               dw1, db1, dw2, db2, pred);
}

// round 4
// speedup vs baseline: 1.1337x; 1.1337x over previous
#include <cuda_runtime.h>
#include <cstdint>

#define N_NODES 50000
#define N_EDGES 800000
#define NFEAT   256
#define NHID    128
#define ZDIM    32
#define NPAIRS  10000

// ---- scratch (static device globals; no allocation at runtime) ----
__device__ float g_buf_h [(size_t)N_NODES * NHID];
__device__ float g_buf_x0[(size_t)N_NODES * NHID];
__device__ float g_buf_x1[(size_t)N_NODES * NHID];
__device__ int   g_rowptr[N_NODES + 1];
__device__ float g_feat[(size_t)NPAIRS * ZDIM];

// ------------------------------------------------------------------
__global__ void rowptr_kernel(const int* __restrict__ row) {
    int r = blockIdx.x * blockDim.x + threadIdx.x;
    if (r > N_NODES) return;
    int lo = 0, hi = N_EDGES;
    while (lo < hi) {
        int mid = (lo + hi) >> 1;
        if (row[mid] < r) lo = mid + 1; else hi = mid;
    }
    g_rowptr[r] = lo;
}

// ------------------------------------------------------------------
// C[M,128] = A[M,K] @ B[K,128]   (BM=128, BN=128, BK=16; 8x8/thread)
// ------------------------------------------------------------------
__global__ __launch_bounds__(256) void sgemm_n128(
    const float* __restrict__ A, const float* __restrict__ B,
    float* __restrict__ C, int M, int K)
{
    __shared__ float As[16][132];
    __shared__ float Bs[16][128];

    int tid = threadIdx.x;
    int tx = tid & 15, ty = tid >> 4;
    int row0 = blockIdx.x * 128;

    float acc[8][8];
#pragma unroll
    for (int i = 0; i < 8; i++)
#pragma unroll
        for (int j = 0; j < 8; j++) acc[i][j] = 0.f;

    for (int k0 = 0; k0 < K; k0 += 16) {
#pragma unroll
        for (int t = 0; t < 8; t++) {
            int i2 = tid + t * 256;
            int r = i2 >> 4, kk = i2 & 15;
            int gr = row0 + r;
            As[kk][r] = (gr < M) ? A[(size_t)gr * K + k0 + kk] : 0.f;
        }
#pragma unroll
        for (int t = 0; t < 8; t++) {
            int i2 = tid + t * 256;
            int kk = i2 >> 7, c = i2 & 127;
            Bs[kk][c] = B[(size_t)(k0 + kk) * 128 + c];
        }
        __syncthreads();

#pragma unroll
        for (int kk = 0; kk < 16; kk++) {
            float a[8], b[8];
#pragma unroll
            for (int i = 0; i < 8; i++) a[i] = As[kk][ty + 16 * i];
#pragma unroll
            for (int j = 0; j < 8; j++) b[j] = Bs[kk][tx + 16 * j];
#pragma unroll
            for (int i = 0; i < 8; i++)
#pragma unroll
                for (int j = 0; j < 8; j++)
                    acc[i][j] = fmaf(a[i], b[j], acc[i][j]);
        }
        __syncthreads();
    }

#pragma unroll
    for (int i = 0; i < 8; i++) {
        int gr = row0 + ty + 16 * i;
        if (gr < M) {
#pragma unroll
            for (int j = 0; j < 8; j++)
                C[(size_t)gr * 128 + tx + 16 * j] = acc[i][j];
        }
    }
}

// ------------------------------------------------------------------
// SpMM with float4 gathers: one warp per destination row
// ------------------------------------------------------------------
__global__ __launch_bounds__(256) void spmm_kernel(
    const float* __restrict__ H, const int* __restrict__ col,
    const float* __restrict__ val, const float* __restrict__ bias,
    const float* __restrict__ res, float* __restrict__ out)
{
    int w = (blockIdx.x * blockDim.x + threadIdx.x) >> 5;
    if (w >= N_NODES) return;
    int lane = threadIdx.x & 31;

    const float4* Hv = (const float4*)H;
    float4 acc = make_float4(0.f, 0.f, 0.f, 0.f);
    int s = g_rowptr[w], e = g_rowptr[w + 1];
    int i = s;
    for (; i + 1 < e; i += 2) {
        int   c0 = __ldg(&col[i]);
        int   c1 = __ldg(&col[i + 1]);
        float v0 = __ldg(&val[i]);
        float v1 = __ldg(&val[i + 1]);
        float4 h0 = __ldg(&Hv[(size_t)c0 * 32 + lane]);
        float4 h1 = __ldg(&Hv[(size_t)c1 * 32 + lane]);
        acc.x = fmaf(v0, h0.x, acc.x); acc.y = fmaf(v0, h0.y, acc.y);
        acc.z = fmaf(v0, h0.z, acc.z); acc.w = fmaf(v0, h0.w, acc.w);
        acc.x = fmaf(v1, h1.x, acc.x); acc.y = fmaf(v1, h1.y, acc.y);
        acc.z = fmaf(v1, h1.z, acc.z); acc.w = fmaf(v1, h1.w, acc.w);
    }
    if (i < e) {
        int   c0 = __ldg(&col[i]);
        float v0 = __ldg(&val[i]);
        float4 h0 = __ldg(&Hv[(size_t)c0 * 32 + lane]);
        acc.x = fmaf(v0, h0.x, acc.x); acc.y = fmaf(v0, h0.y, acc.y);
        acc.z = fmaf(v0, h0.z, acc.z); acc.w = fmaf(v0, h0.w, acc.w);
    }

    float4 bb = __ldg(&((const float4*)bias)[lane]);
    float4 o;
    o.x = fmaxf(acc.x + bb.x, 0.f);
    o.y = fmaxf(acc.y + bb.y, 0.f);
    o.z = fmaxf(acc.z + bb.z, 0.f);
    o.w = fmaxf(acc.w + bb.w, 0.f);
    size_t vbase = (size_t)w * 32 + lane;
    if (res) {
        float4 rv = __ldg(&((const float4*)res)[vbase]);
        o.x += rv.x; o.y += rv.y; o.z += rv.z; o.w += rv.w;
    }
    ((float4*)out)[vbase] = o;
}

// ------------------------------------------------------------------
// tf32 helpers
// ------------------------------------------------------------------
__device__ __forceinline__ float f2tf32(float x) {
    uint32_t u;
    asm("cvt.rna.tf32.f32 %0, %1;" : "=r"(u) : "f"(x));
    return __uint_as_float(u);
}

__device__ __forceinline__ void mma_tf32(
    float& d0, float& d1, float& d2, float& d3,
    uint32_t a0, uint32_t a1, uint32_t a2, uint32_t a3,
    uint32_t b0, uint32_t b1)
{
    asm volatile(
        "mma.sync.aligned.m16n8k8.row.col.f32.tf32.tf32.f32 "
        "{%0,%1,%2,%3}, {%4,%5,%6,%7}, {%8,%9}, {%0,%1,%2,%3};\n"
        : "+f"(d0), "+f"(d1), "+f"(d2), "+f"(d3)
        : "r"(a0), "r"(a1), "r"(a2), "r"(a3), "r"(b0), "r"(b1));
}

// ------------------------------------------------------------------
// Bilinear stage 1: tile = 128 pairs x (KC k-slices), split-tf32 (3-MMA).
// U = A @ W_k with A = Ab+As (registers), W = Wb+Ws (two smem planes).
// U ≈ Ab·Wb + As·Wb + Ab·Ws  (fp32-quality). feat[p,k] = dot(U[p,:],B[p,:]).
// Warp map: 8 warps x 16 M-rows each, full N=128 per warp.
// Dyn smem: sA[128][132] fp32 | sB[128][132] fp32 | sWb[32][136] | sWs[32][136]
// ------------------------------------------------------------------
#define KC 4
#define BIL_SMEM_FLOATS (128 * 132 + 128 * 132 + 2 * 32 * 136)
#define BIL_SMEM_BYTES  (BIL_SMEM_FLOATS * 4)

__global__ __launch_bounds__(256, 1) void bilinear_kernel(
    const float* __restrict__ latent, const int* __restrict__ idx,
    const float* __restrict__ bilw, float* __restrict__ feat)
{
    extern __shared__ float smem[];
    float* sA  = smem;                      // [128][132] fp32 a rows
    float* sB  = sA + 128 * 132;            // [128][132] fp32 b rows
    float* sWb = sB + 128 * 132;            // [32][136]  tf32 big plane
    float* sWs = sWb + 32 * 136;            // [32][136]  tf32 small plane

    int tid  = threadIdx.x;
    int lane = tid & 31, warp = tid >> 5;
    int p0 = blockIdx.x * 128;
    int g = lane >> 2, t4 = lane & 3;
    int r0 = warp * 16 + g;                 // warps 0..7 cover rows 0..127

    // gather A and B pair rows (fp32)
    for (int i = tid; i < 128 * 32; i += 256) {
        int p = i >> 5, c8 = (i & 31) * 4;
        int pg = p0 + p; if (pg >= NPAIRS) pg = NPAIRS - 1;
        int na = __ldg(&idx[pg]);
        int nb = __ldg(&idx[NPAIRS + pg]);
        float4 va = __ldg((const float4*)(latent + (size_t)na * 128 + c8));
        float4 vb = __ldg((const float4*)(latent + (size_t)nb * 128 + c8));
        *(float4*)&sA[p * 132 + c8] = va;
        *(float4*)&sB[p * 132 + c8] = vb;
    }

    for (int kk = 0; kk < KC; kk++) {
        int k = blockIdx.y * KC + kk;

        float acc[16][4];
#pragma unroll
        for (int nt = 0; nt < 16; nt++)
#pragma unroll
            for (int j = 0; j < 4; j++) acc[nt][j] = 0.f;

        for (int k0 = 0; k0 < 128; k0 += 32) {
            __syncthreads();   // sA/sB ready (1st iter); sW planes free (later)
            for (int i = tid; i < 32 * 32; i += 256) {
                int dd = i >> 5, c8 = (i & 31) * 4;
                const float* wp = bilw + ((size_t)k * 128 + k0 + dd) * 128 + c8;
                float4 w4 = __ldg((const float4*)wp);
                float wb0 = f2tf32(w4.x), wb1 = f2tf32(w4.y);
                float wb2 = f2tf32(w4.z), wb3 = f2tf32(w4.w);
                sWb[dd * 136 + c8 + 0] = wb0;
                sWb[dd * 136 + c8 + 1] = wb1;
                sWb[dd * 136 + c8 + 2] = wb2;
                sWb[dd * 136 + c8 + 3] = wb3;
                sWs[dd * 136 + c8 + 0] = f2tf32(w4.x - wb0);
                sWs[dd * 136 + c8 + 1] = f2tf32(w4.y - wb1);
                sWs[dd * 136 + c8 + 2] = f2tf32(w4.z - wb2);
                sWs[dd * 136 + c8 + 3] = f2tf32(w4.w - wb3);
            }
            __syncthreads();

#pragma unroll
            for (int ks = 0; ks < 32; ks += 8) {
                // A fragment: load fp32, split into big/small in registers
                float af0 = sA[(r0    ) * 132 + k0 + ks + t4    ];
                float af1 = sA[(r0 + 8) * 132 + k0 + ks + t4    ];
                float af2 = sA[(r0    ) * 132 + k0 + ks + t4 + 4];
                float af3 = sA[(r0 + 8) * 132 + k0 + ks + t4 + 4];
                float ab0f = f2tf32(af0), ab1f = f2tf32(af1);
                float ab2f = f2tf32(af2), ab3f = f2tf32(af3);
                uint32_t ab0 = __float_as_uint(ab0f);
                uint32_t ab1 = __float_as_uint(ab1f);
                uint32_t ab2 = __float_as_uint(ab2f);
                uint32_t ab3 = __float_as_uint(ab3f);
                uint32_t as0 = __float_as_uint(f2tf32(af0 - ab0f));
                uint32_t as1 = __float_as_uint(f2tf32(af1 - ab1f));
                uint32_t as2 = __float_as_uint(f2tf32(af2 - ab2f));
                uint32_t as3 = __float_as_uint(f2tf32(af3 - ab3f));
#pragma unroll
                for (int nt = 0; nt < 16; nt++) {
                    int e = nt * 8 + g;
                    uint32_t bb0 = __float_as_uint(sWb[(ks + t4    ) * 136 + e]);
                    uint32_t bb1 = __float_as_uint(sWb[(ks + t4 + 4) * 136 + e]);
                    uint32_t bs0 = __float_as_uint(sWs[(ks + t4    ) * 136 + e]);
                    uint32_t bs1 = __float_as_uint(sWs[(ks + t4 + 4) * 136 + e]);
                    // Ab*Wb + As*Wb + Ab*Ws
                    mma_tf32(acc[nt][0], acc[nt][1], acc[nt][2], acc[nt][3],
                             ab0, ab1, ab2, ab3, bb0, bb1);
                    mma_tf32(acc[nt][0], acc[nt][1], acc[nt][2], acc[nt][3],
                             as0, as1, as2, as3, bb0, bb1);
                    mma_tf32(acc[nt][0], acc[nt][1], acc[nt][2], acc[nt][3],
                             ab0, ab1, ab2, ab3, bs0, bs1);
                }
            }
        }

        // epilogue: each warp fully owns rows r0 / r0+8 -> plain reduce
        float plo = 0.f, phi = 0.f;
#pragma unroll
        for (int nt = 0; nt < 16; nt++) {
            int c = nt * 8 + 2 * t4;
            plo = fmaf(acc[nt][0], sB[(r0    ) * 132 + c    ], plo);
            plo = fmaf(acc[nt][1], sB[(r0    ) * 132 + c + 1], plo);
            phi = fmaf(acc[nt][2], sB[(r0 + 8) * 132 + c    ], phi);
            phi = fmaf(acc[nt][3], sB[(r0 + 8) * 132 + c + 1], phi);
        }
        plo += __shfl_xor_sync(0xffffffffu, plo, 1);
        plo += __shfl_xor_sync(0xffffffffu, plo, 2);
        phi += __shfl_xor_sync(0xffffffffu, phi, 1);
        phi += __shfl_xor_sync(0xffffffffu, phi, 2);
        if (t4 == 0) {
            int pg0 = p0 + r0;
            int pg1 = p0 + r0 + 8;
            if (pg0 < NPAIRS) feat[(size_t)pg0 * ZDIM + k] = plo;
            if (pg1 < NPAIRS) feat[(size_t)pg1 * ZDIM + k] = phi;
        }
    }
}

// ------------------------------------------------------------------
// Stage 2: tiny MLP on feat -> predictions
// ------------------------------------------------------------------
__device__ __forceinline__ float elu1(float x) {
    return x > 0.f ? x : expm1f(x);
}

__global__ __launch_bounds__(256) void mlp_kernel(
    const float* __restrict__ feat, const float* __restrict__ bilb,
    const float* __restrict__ dw1, const float* __restrict__ db1,
    const float* __restrict__ dw2, const float* __restrict__ db2,
    float* __restrict__ pred)
{
    int p = blockIdx.x * blockDim.x + threadIdx.x;
    if (p >= NPAIRS) return;

    float f[ZDIM];
#pragma unroll
    for (int k = 0; k < ZDIM; k++)
        f[k] = elu1(feat[(size_t)p * ZDIM + k] + __ldg(&bilb[k]));

    float o = __ldg(&db2[0]);
#pragma unroll
    for (int kk = 0; kk < ZDIM; kk++) {
        float s = __ldg(&db1[kk]);
#pragma unroll
        for (int j = 0; j < ZDIM; j++)
            s = fmaf(f[j], __ldg(&dw1[j * ZDIM + kk]), s);
        o = fmaf(elu1(s), __ldg(&dw2[kk]), o);
    }
    pred[p] = o;
}

// ------------------------------------------------------------------
extern "C" void kernel_launch(void* const* d_in, const int* in_sizes, int n_in,
                              void* d_out, int out_size)
{
    const float* features = (const float*)d_in[0];
    const int*   adj_row  = (const int*)  d_in[1];
    const int*   adj_col  = (const int*)  d_in[2];
    const float* adj_val  = (const float*)d_in[3];
    const int*   idx      = (const int*)  d_in[4];
    const float* W0   = (const float*)d_in[5];
    const float* b0   = (const float*)d_in[6];
    const float* W1   = (const float*)d_in[7];
    const float* b1   = (const float*)d_in[8];
    const float* W2   = (const float*)d_in[9];
    const float* b2   = (const float*)d_in[10];
    const float* bilw = (const float*)d_in[11];
    const float* bilb = (const float*)d_in[12];
    const float* dw1  = (const float*)d_in[13];
    const float* db1  = (const float*)d_in[14];
    const float* dw2  = (const float*)d_in[15];
    const float* db2  = (const float*)d_in[16];

    float* out    = (float*)d_out;
    float* pred   = out;            // [NPAIRS]
    float* latent = out + NPAIRS;   // [N_NODES * NHID]

    float* h;  cudaGetSymbolAddress((void**)&h,  g_buf_h);
    float* x0; cudaGetSymbolAddress((void**)&x0, g_buf_x0);
    float* x1; cudaGetSymbolAddress((void**)&x1, g_buf_x1);
    float* ft; cudaGetSymbolAddress((void**)&ft, g_feat);

    static int smem_set = 0;
    if (!smem_set) {
        cudaFuncSetAttribute(bilinear_kernel,
                             cudaFuncAttributeMaxDynamicSharedMemorySize,
                             BIL_SMEM_BYTES);
        smem_set = 1;
    }

    rowptr_kernel<<<(N_NODES + 1 + 255) / 256, 256>>>(adj_row);

    const int gemm_grid = (N_NODES + 127) / 128;
    const int spmm_grid = (N_NODES * 32 + 255) / 256;

    sgemm_n128<<<gemm_grid, 256>>>(features, W0, h, N_NODES, NFEAT);
    spmm_kernel<<<spmm_grid, 256>>>(h, adj_col, adj_val, b0, nullptr, x0);

    sgemm_n128<<<gemm_grid, 256>>>(x0, W1, h, N_NODES, NHID);
    spmm_kernel<<<spmm_grid, 256>>>(h, adj_col, adj_val, b1, x0, x1);

    sgemm_n128<<<gemm_grid, 256>>>(x1, W2, h, N_NODES, NHID);
    spmm_kernel<<<spmm_grid, 256>>>(h, adj_col, adj_val, b2, x1, latent);

    dim3 bil_grid((NPAIRS + 127) / 128, ZDIM / KC);
    bilinear_kernel<<<bil_grid, 256, BIL_SMEM_BYTES>>>(latent, idx, bilw, ft);
    mlp_kernel<<<(NPAIRS + 255) / 256, 256>>>(ft, bilb, dw1, db1, dw2, db2, pred);
}

// round 5
// speedup vs baseline: 1.9665x; 1.7346x over previous
#include <cuda_runtime.h>
#include <cstdint>

#define N_NODES 50000
#define N_EDGES 800000
#define NFEAT   256
#define NHID    128
#define ZDIM    32
#define NPAIRS  10000

// ---- scratch (static device globals; no allocation at runtime) ----
__device__ float g_buf_h [(size_t)N_NODES * NHID];
__device__ float g_buf_x0[(size_t)N_NODES * NHID];
__device__ float g_buf_x1[(size_t)N_NODES * NHID];
__device__ int   g_rowptr[N_NODES + 1];
__device__ float g_feat[(size_t)NPAIRS * ZDIM];

// ------------------------------------------------------------------
__global__ void rowptr_kernel(const int* __restrict__ row) {
    int r = blockIdx.x * blockDim.x + threadIdx.x;
    if (r > N_NODES) return;
    int lo = 0, hi = N_EDGES;
    while (lo < hi) {
        int mid = (lo + hi) >> 1;
        if (row[mid] < r) lo = mid + 1; else hi = mid;
    }
    g_rowptr[r] = lo;
}

// ------------------------------------------------------------------
// bf16 split helpers
// ------------------------------------------------------------------
__device__ __forceinline__ uint32_t pack2bf(float lo, float hi) {
    uint32_t r;
    asm("cvt.rn.bf16x2.f32 %0, %1, %2;" : "=r"(r) : "f"(hi), "f"(lo));
    return r;
}
__device__ __forceinline__ float2 unpack_bf(uint32_t p) {
    return make_float2(__uint_as_float(p << 16),
                       __uint_as_float(p & 0xffff0000u));
}

__device__ __forceinline__ void mma_bf16(
    float* d, uint32_t a0, uint32_t a1, uint32_t a2, uint32_t a3,
    uint32_t b0, uint32_t b1)
{
    asm volatile(
        "mma.sync.aligned.m16n8k16.row.col.f32.bf16.bf16.f32 "
        "{%0,%1,%2,%3}, {%4,%5,%6,%7}, {%8,%9}, {%0,%1,%2,%3};\n"
        : "+f"(d[0]), "+f"(d[1]), "+f"(d[2]), "+f"(d[3])
        : "r"(a0), "r"(a1), "r"(a2), "r"(a3), "r"(b0), "r"(b1));
}

// ------------------------------------------------------------------
// Encoder GEMM: C[M,128] = A[M,K] @ B[K,128], split-bf16 3-MMA.
// BM=128, BK=32, 256 threads, 8 warps x 16 rows x full N=128.
// ------------------------------------------------------------------
__global__ __launch_bounds__(256, 2) void gemm_bf16_n128(
    const float* __restrict__ A, const float* __restrict__ B,
    float* __restrict__ C, int M, int K)
{
    __shared__ uint32_t sAb[128][17], sAs[128][17];   // [row][kpair]
    __shared__ uint32_t sBb[16][136], sBs[16][136];   // [kpair][col]

    int tid  = threadIdx.x;
    int lane = tid & 31, warp = tid >> 5;
    int g = lane >> 2, t4 = lane & 3;
    int r0 = warp * 16 + g;
    int row0 = blockIdx.x * 128;

    float acc[16][4];
#pragma unroll
    for (int nt = 0; nt < 16; nt++)
#pragma unroll
        for (int j = 0; j < 4; j++) acc[nt][j] = 0.f;

    for (int k0 = 0; k0 < K; k0 += 32) {
        __syncthreads();
        // A tile: 128 rows x 32 k, split+pack along k
#pragma unroll
        for (int u = 0; u < 4; u++) {
            int i = tid + u * 256;
            int r = i >> 3, q = i & 7;
            int gr = row0 + r;
            float4 v = (gr < M)
                ? __ldg((const float4*)(A + (size_t)gr * K + k0 + 4 * q))
                : make_float4(0.f, 0.f, 0.f, 0.f);
            uint32_t p0 = pack2bf(v.x, v.y);
            uint32_t p1 = pack2bf(v.z, v.w);
            float2 f0 = unpack_bf(p0), f1 = unpack_bf(p1);
            sAb[r][2 * q]     = p0;
            sAb[r][2 * q + 1] = p1;
            sAs[r][2 * q]     = pack2bf(v.x - f0.x, v.y - f0.y);
            sAs[r][2 * q + 1] = pack2bf(v.z - f1.x, v.w - f1.y);
        }
        // B tile: 32 k x 128 cols, pack pairs along k
#pragma unroll
        for (int u = 0; u < 2; u++) {
            int i = tid + u * 256;
            int kp = i >> 5, c4 = (i & 31) * 4;
            float4 w0 = __ldg((const float4*)(B + (size_t)(k0 + 2 * kp) * 128 + c4));
            float4 w1 = __ldg((const float4*)(B + (size_t)(k0 + 2 * kp + 1) * 128 + c4));
            float lo[4] = {w0.x, w0.y, w0.z, w0.w};
            float hi[4] = {w1.x, w1.y, w1.z, w1.w};
#pragma unroll
            for (int j = 0; j < 4; j++) {
                uint32_t pb = pack2bf(lo[j], hi[j]);
                float2 f = unpack_bf(pb);
                sBb[kp][c4 + j] = pb;
                sBs[kp][c4 + j] = pack2bf(lo[j] - f.x, hi[j] - f.y);
            }
        }
        __syncthreads();

#pragma unroll
        for (int ks = 0; ks < 2; ks++) {
            int kp0 = ks * 8;
            uint32_t ab0 = sAb[r0    ][kp0 + t4];
            uint32_t ab1 = sAb[r0 + 8][kp0 + t4];
            uint32_t ab2 = sAb[r0    ][kp0 + t4 + 4];
            uint32_t ab3 = sAb[r0 + 8][kp0 + t4 + 4];
            uint32_t as0 = sAs[r0    ][kp0 + t4];
            uint32_t as1 = sAs[r0 + 8][kp0 + t4];
            uint32_t as2 = sAs[r0    ][kp0 + t4 + 4];
            uint32_t as3 = sAs[r0 + 8][kp0 + t4 + 4];
#pragma unroll
            for (int nt = 0; nt < 16; nt++) {
                int e = nt * 8 + g;
                uint32_t bb0 = sBb[kp0 + t4    ][e];
                uint32_t bb1 = sBb[kp0 + t4 + 4][e];
                uint32_t bs0 = sBs[kp0 + t4    ][e];
                uint32_t bs1 = sBs[kp0 + t4 + 4][e];
                mma_bf16(acc[nt], ab0, ab1, ab2, ab3, bb0, bb1);
                mma_bf16(acc[nt], as0, as1, as2, as3, bb0, bb1);
                mma_bf16(acc[nt], ab0, ab1, ab2, ab3, bs0, bs1);
            }
        }
    }

#pragma unroll
    for (int nt = 0; nt < 16; nt++) {
        int c = nt * 8 + 2 * t4;
        int gr0 = row0 + r0, gr1 = gr0 + 8;
        if (gr0 < M)
            *(float2*)(C + (size_t)gr0 * 128 + c) = make_float2(acc[nt][0], acc[nt][1]);
        if (gr1 < M)
            *(float2*)(C + (size_t)gr1 * 128 + c) = make_float2(acc[nt][2], acc[nt][3]);
    }
}

// ------------------------------------------------------------------
// SpMM with float4 gathers: one warp per destination row
// ------------------------------------------------------------------
__global__ __launch_bounds__(256) void spmm_kernel(
    const float* __restrict__ H, const int* __restrict__ col,
    const float* __restrict__ val, const float* __restrict__ bias,
    const float* __restrict__ res, float* __restrict__ out)
{
    int w = (blockIdx.x * blockDim.x + threadIdx.x) >> 5;
    if (w >= N_NODES) return;
    int lane = threadIdx.x & 31;

    const float4* Hv = (const float4*)H;
    float4 acc = make_float4(0.f, 0.f, 0.f, 0.f);
    int s = g_rowptr[w], e = g_rowptr[w + 1];
    int i = s;
    for (; i + 1 < e; i += 2) {
        int   c0 = __ldg(&col[i]);
        int   c1 = __ldg(&col[i + 1]);
        float v0 = __ldg(&val[i]);
        float v1 = __ldg(&val[i + 1]);
        float4 h0 = __ldg(&Hv[(size_t)c0 * 32 + lane]);
        float4 h1 = __ldg(&Hv[(size_t)c1 * 32 + lane]);
        acc.x = fmaf(v0, h0.x, acc.x); acc.y = fmaf(v0, h0.y, acc.y);
        acc.z = fmaf(v0, h0.z, acc.z); acc.w = fmaf(v0, h0.w, acc.w);
        acc.x = fmaf(v1, h1.x, acc.x); acc.y = fmaf(v1, h1.y, acc.y);
        acc.z = fmaf(v1, h1.z, acc.z); acc.w = fmaf(v1, h1.w, acc.w);
    }
    if (i < e) {
        int   c0 = __ldg(&col[i]);
        float v0 = __ldg(&val[i]);
        float4 h0 = __ldg(&Hv[(size_t)c0 * 32 + lane]);
        acc.x = fmaf(v0, h0.x, acc.x); acc.y = fmaf(v0, h0.y, acc.y);
        acc.z = fmaf(v0, h0.z, acc.z); acc.w = fmaf(v0, h0.w, acc.w);
    }

    float4 bb = __ldg(&((const float4*)bias)[lane]);
    float4 o;
    o.x = fmaxf(acc.x + bb.x, 0.f);
    o.y = fmaxf(acc.y + bb.y, 0.f);
    o.z = fmaxf(acc.z + bb.z, 0.f);
    o.w = fmaxf(acc.w + bb.w, 0.f);
    size_t vbase = (size_t)w * 32 + lane;
    if (res) {
        float4 rv = __ldg(&((const float4*)res)[vbase]);
        o.x += rv.x; o.y += rv.y; o.z += rv.z; o.w += rv.w;
    }
    ((float4*)out)[vbase] = o;
}

// ------------------------------------------------------------------
// Bilinear stage 1: tile = 128 pairs x (KC k-slices), split-bf16 3-MMA.
// U = A @ W_k; feat[p,k] = dot(U[p,:], B[p,:]).
// Warp map: 8 warps x 16 M-rows each, full N=128 per warp.
// Dyn smem: sA[128][132] f32 | sB[128][132] f32 | sWb[16][136] | sWs[16][136]
// ------------------------------------------------------------------
#define KC 4
#define BIL_SMEM_WORDS (128 * 132 + 128 * 132 + 2 * 16 * 136)
#define BIL_SMEM_BYTES (BIL_SMEM_WORDS * 4)

__global__ __launch_bounds__(256, 1) void bilinear_kernel(
    const float* __restrict__ latent, const int* __restrict__ idx,
    const float* __restrict__ bilw, float* __restrict__ feat)
{
    extern __shared__ float smem[];
    float*    sA  = smem;                          // [128][132] fp32 a rows
    float*    sB  = sA + 128 * 132;                // [128][132] fp32 b rows
    uint32_t* sWb = (uint32_t*)(sB + 128 * 132);   // [16 kpair][136] big
    uint32_t* sWs = sWb + 16 * 136;                // [16 kpair][136] small

    int tid  = threadIdx.x;
    int lane = tid & 31, warp = tid >> 5;
    int p0 = blockIdx.x * 128;
    int g = lane >> 2, t4 = lane & 3;
    int r0 = warp * 16 + g;                        // warps 0..7 cover rows 0..127

    // gather A and B pair rows (fp32)
    for (int i = tid; i < 128 * 32; i += 256) {
        int p = i >> 5, c8 = (i & 31) * 4;
        int pg = p0 + p; if (pg >= NPAIRS) pg = NPAIRS - 1;
        int na = __ldg(&idx[pg]);
        int nb = __ldg(&idx[NPAIRS + pg]);
        float4 va = __ldg((const float4*)(latent + (size_t)na * 128 + c8));
        float4 vb = __ldg((const float4*)(latent + (size_t)nb * 128 + c8));
        *(float4*)&sA[p * 132 + c8] = va;
        *(float4*)&sB[p * 132 + c8] = vb;
    }

    for (int kk = 0; kk < KC; kk++) {
        int k = blockIdx.y * KC + kk;

        float acc[16][4];
#pragma unroll
        for (int nt = 0; nt < 16; nt++)
#pragma unroll
            for (int j = 0; j < 4; j++) acc[nt][j] = 0.f;

        for (int k0 = 0; k0 < 128; k0 += 32) {
            __syncthreads();   // sA/sB ready (1st iter); sW planes free (later)
            // load W chunk [32 d][128 e], pack pairs along d
#pragma unroll
            for (int u = 0; u < 2; u++) {
                int i = tid + u * 256;
                int kp = i >> 5, c4 = (i & 31) * 4;
                const float* wp0 = bilw + ((size_t)k * 128 + k0 + 2 * kp) * 128 + c4;
                float4 w0 = __ldg((const float4*)wp0);
                float4 w1 = __ldg((const float4*)(wp0 + 128));
                float lo[4] = {w0.x, w0.y, w0.z, w0.w};
                float hi[4] = {w1.x, w1.y, w1.z, w1.w};
#pragma unroll
                for (int j = 0; j < 4; j++) {
                    uint32_t pb = pack2bf(lo[j], hi[j]);
                    float2 f = unpack_bf(pb);
                    sWb[kp * 136 + c4 + j] = pb;
                    sWs[kp * 136 + c4 + j] = pack2bf(lo[j] - f.x, hi[j] - f.y);
                }
            }
            __syncthreads();

#pragma unroll
            for (int ks = 0; ks < 2; ks++) {
                int cb = k0 + ks * 16 + 2 * t4;
                // A fragments from fp32 smem, split+pack in registers
                float xl0 = sA[(r0    ) * 132 + cb],     xh0 = sA[(r0    ) * 132 + cb + 1];
                float xl1 = sA[(r0 + 8) * 132 + cb],     xh1 = sA[(r0 + 8) * 132 + cb + 1];
                float xl2 = sA[(r0    ) * 132 + cb + 8], xh2 = sA[(r0    ) * 132 + cb + 9];
                float xl3 = sA[(r0 + 8) * 132 + cb + 8], xh3 = sA[(r0 + 8) * 132 + cb + 9];
                uint32_t ab0 = pack2bf(xl0, xh0);
                uint32_t ab1 = pack2bf(xl1, xh1);
                uint32_t ab2 = pack2bf(xl2, xh2);
                uint32_t ab3 = pack2bf(xl3, xh3);
                float2 f0 = unpack_bf(ab0), f1 = unpack_bf(ab1);
                float2 f2 = unpack_bf(ab2), f3 = unpack_bf(ab3);
                uint32_t as0 = pack2bf(xl0 - f0.x, xh0 - f0.y);
                uint32_t as1 = pack2bf(xl1 - f1.x, xh1 - f1.y);
                uint32_t as2 = pack2bf(xl2 - f2.x, xh2 - f2.y);
                uint32_t as3 = pack2bf(xl3 - f3.x, xh3 - f3.y);
                int kp0 = ks * 8;
#pragma unroll
                for (int nt = 0; nt < 16; nt++) {
                    int e = nt * 8 + g;
                    uint32_t bb0 = sWb[(kp0 + t4    ) * 136 + e];
                    uint32_t bb1 = sWb[(kp0 + t4 + 4) * 136 + e];
                    uint32_t bs0 = sWs[(kp0 + t4    ) * 136 + e];
                    uint32_t bs1 = sWs[(kp0 + t4 + 4) * 136 + e];
                    mma_bf16(acc[nt], ab0, ab1, ab2, ab3, bb0, bb1);
                    mma_bf16(acc[nt], as0, as1, as2, as3, bb0, bb1);
                    mma_bf16(acc[nt], ab0, ab1, ab2, ab3, bs0, bs1);
                }
            }
        }

        // epilogue: each warp fully owns rows r0 / r0+8 -> plain reduce
        float plo = 0.f, phi = 0.f;
#pragma unroll
        for (int nt = 0; nt < 16; nt++) {
            int c = nt * 8 + 2 * t4;
            plo = fmaf(acc[nt][0], sB[(r0    ) * 132 + c    ], plo);
            plo = fmaf(acc[nt][1], sB[(r0    ) * 132 + c + 1], plo);
            phi = fmaf(acc[nt][2], sB[(r0 + 8) * 132 + c    ], phi);
            phi = fmaf(acc[nt][3], sB[(r0 + 8) * 132 + c + 1], phi);
        }
        plo += __shfl_xor_sync(0xffffffffu, plo, 1);
        plo += __shfl_xor_sync(0xffffffffu, plo, 2);
        phi += __shfl_xor_sync(0xffffffffu, phi, 1);
        phi += __shfl_xor_sync(0xffffffffu, phi, 2);
        if (t4 == 0) {
            int pg0 = p0 + r0;
            int pg1 = p0 + r0 + 8;
            if (pg0 < NPAIRS) feat[(size_t)pg0 * ZDIM + k] = plo;
            if (pg1 < NPAIRS) feat[(size_t)pg1 * ZDIM + k] = phi;
        }
    }
}

// ------------------------------------------------------------------
// Stage 2: tiny MLP on feat -> predictions
// ------------------------------------------------------------------
__device__ __forceinline__ float elu1(float x) {
    return x > 0.f ? x : expm1f(x);
}

__global__ __launch_bounds__(256) void mlp_kernel(
    const float* __restrict__ feat, const float* __restrict__ bilb,
    const float* __restrict__ dw1, const float* __restrict__ db1,
    const float* __restrict__ dw2, const float* __restrict__ db2,
    float* __restrict__ pred)
{
    int p = blockIdx.x * blockDim.x + threadIdx.x;
    if (p >= NPAIRS) return;

    float f[ZDIM];
#pragma unroll
    for (int k = 0; k < ZDIM; k++)
        f[k] = elu1(feat[(size_t)p * ZDIM + k] + __ldg(&bilb[k]));

    float o = __ldg(&db2[0]);
#pragma unroll
    for (int kk = 0; kk < ZDIM; kk++) {
        float s = __ldg(&db1[kk]);
#pragma unroll
        for (int j = 0; j < ZDIM; j++)
            s = fmaf(f[j], __ldg(&dw1[j * ZDIM + kk]), s);
        o = fmaf(elu1(s), __ldg(&dw2[kk]), o);
    }
    pred[p] = o;
}

// ------------------------------------------------------------------
extern "C" void kernel_launch(void* const* d_in, const int* in_sizes, int n_in,
                              void* d_out, int out_size)
{
    const float* features = (const float*)d_in[0];
    const int*   adj_row  = (const int*)  d_in[1];
    const int*   adj_col  = (const int*)  d_in[2];
    const float* adj_val  = (const float*)d_in[3];
    const int*   idx      = (const int*)  d_in[4];
    const float* W0   = (const float*)d_in[5];
    const float* b0   = (const float*)d_in[6];
    const float* W1   = (const float*)d_in[7];
    const float* b1   = (const float*)d_in[8];
    const float* W2   = (const float*)d_in[9];
    const float* b2   = (const float*)d_in[10];
    const float* bilw = (const float*)d_in[11];
    const float* bilb = (const float*)d_in[12];
    const float* dw1  = (const float*)d_in[13];
    const float* db1  = (const float*)d_in[14];
    const float* dw2  = (const float*)d_in[15];
    const float* db2  = (const float*)d_in[16];

    float* out    = (float*)d_out;
    float* pred   = out;            // [NPAIRS]
    float* latent = out + NPAIRS;   // [N_NODES * NHID]

    float* h;  cudaGetSymbolAddress((void**)&h,  g_buf_h);
    float* x0; cudaGetSymbolAddress((void**)&x0, g_buf_x0);
    float* x1; cudaGetSymbolAddress((void**)&x1, g_buf_x1);
    float* ft; cudaGetSymbolAddress((void**)&ft, g_feat);

    static int smem_set = 0;
    if (!smem_set) {
        cudaFuncSetAttribute(bilinear_kernel,
                             cudaFuncAttributeMaxDynamicSharedMemorySize,
                             BIL_SMEM_BYTES);
        smem_set = 1;
    }

    rowptr_kernel<<<(N_NODES + 1 + 255) / 256, 256>>>(adj_row);

    const int gemm_grid = (N_NODES + 127) / 128;
    const int spmm_grid = (N_NODES * 32 + 255) / 256;

    gemm_bf16_n128<<<gemm_grid, 256>>>(features, W0, h, N_NODES, NFEAT);
    spmm_kernel<<<spmm_grid, 256>>>(h, adj_col, adj_val, b0, nullptr, x0);

    gemm_bf16_n128<<<gemm_grid, 256>>>(x0, W1, h, N_NODES, NHID);
    spmm_kernel<<<spmm_grid, 256>>>(h, adj_col, adj_val, b1, x0, x1);

    gemm_bf16_n128<<<gemm_grid, 256>>>(x1, W2, h, N_NODES, NHID);
    spmm_kernel<<<spmm_grid, 256>>>(h, adj_col, adj_val, b2, x1, latent);

    dim3 bil_grid((NPAIRS + 127) / 128, ZDIM / KC);
    bilinear_kernel<<<bil_grid, 256, BIL_SMEM_BYTES>>>(latent, idx, bilw, ft);
    mlp_kernel<<<(NPAIRS + 255) / 256, 256>>>(ft, bilb, dw1, db1, dw2, db2, pred);
}